// round 1
// baseline (speedup 1.0000x reference)
#include <cuda_runtime.h>
#include <cstdint>

#define BB   32
#define SS   2048
#define ENCD 1024
#define DECD 1024

// Scratch (allocation-free rule: __device__ globals)
__device__ float g_scores[BB * SS];
__device__ float g_decb[BB * DECD];

__device__ __forceinline__ float fast_tanh(float x) {
    float y;
    asm("tanh.approx.f32 %0, %1;" : "=f"(y) : "f"(x));
    return y;
}
__device__ __forceinline__ unsigned f2tf32(float x) {
    unsigned o;
    asm("cvt.rna.tf32.f32 %0, %1;" : "=r"(o) : "f"(x));
    return o;
}

// ---------------------------------------------------------------------------
// Kernel 1: dec_base[b][d] = decoder_hidden[b] @ W_dec[:,d] + b_attn[d]
//           + zero g_scores and context region of d_out
// ---------------------------------------------------------------------------
__global__ void prep_kernel(const float* __restrict__ dh,
                            const float* __restrict__ W,      // full W_attn (2048,1024)
                            const float* __restrict__ b_attn,
                            float* __restrict__ out_ctx) {
    const int b = blockIdx.x;
    const int tid = threadIdx.x;

    // zero scratch + context output region (stream-ordered before consumers)
    for (int i = b * 256 + tid; i < BB * SS; i += 32 * 256) g_scores[i] = 0.f;
    for (int i = b * 256 + tid; i < BB * ENCD; i += 32 * 256) out_ctx[i] = 0.f;

    __shared__ float sh[DECD];
    for (int i = tid; i < DECD; i += 256) sh[i] = dh[b * DECD + i];
    __syncthreads();

    const int d0 = tid;                       // covers d0, d0+256, d0+512, d0+768
    float a0 = b_attn[d0];
    float a1 = b_attn[d0 + 256];
    float a2 = b_attn[d0 + 512];
    float a3 = b_attn[d0 + 768];

#pragma unroll 4
    for (int e = 0; e < DECD; e++) {
        const float sv = sh[e];
        const float* w = W + (size_t)e * DECD + d0;
        a0 += sv * w[0];
        a1 += sv * w[256];
        a2 += sv * w[512];
        a3 += sv * w[768];
    }
    g_decb[b * DECD + d0]       = a0;
    g_decb[b * DECD + d0 + 256] = a1;
    g_decb[b * DECD + d0 + 512] = a2;
    g_decb[b * DECD + d0 + 768] = a3;
}

// ---------------------------------------------------------------------------
// Kernel 2: fused enc_proj GEMM (tf32 mma.sync) + tanh + v-dot -> score partials
//   A = encoder_outputs as (65536 x 1024) row-major
//   Bmat = W_enc = W_attn rows [1024:2048]  (1024 x 1024), row-major [k][n]
//   Block tile: 128(M) x 128(N), BK=32, 8 warps in 4(M) x 2(N)
//   grid = (8 n-tiles, 512 m-tiles); each m-tile is inside a single batch.
// ---------------------------------------------------------------------------
__global__ __launch_bounds__(256, 2) void score_gemm_kernel(
        const float* __restrict__ enc,
        const float* __restrict__ W,        // full W_attn
        const float* __restrict__ vw) {
    __shared__ float As[128][33];           // [m][k]
    __shared__ float Bs[32][132];           // [k][n]

    const int tid  = threadIdx.x;
    const int lane = tid & 31;
    const int warp = tid >> 5;
    const int wm   = warp >> 1;             // 0..3
    const int wn   = warp & 1;              // 0..1
    const int m0   = blockIdx.y * 128;
    const int n0   = blockIdx.x * 128;

    float acc[2][8][4];
#pragma unroll
    for (int i = 0; i < 2; i++)
#pragma unroll
        for (int j = 0; j < 8; j++)
#pragma unroll
            for (int c = 0; c < 4; c++) acc[i][j][c] = 0.f;

    for (int kt = 0; kt < 1024; kt += 32) {
        // Load A tile 128x32 (converted to tf32 bits)
#pragma unroll
        for (int i = 0; i < 4; i++) {
            const int q = tid + i * 256;        // 0..1023
            const int r = q >> 3;               // 0..127
            const int c = (q & 7) * 4;          // 0..28
            const float4 v = *(const float4*)(enc + (size_t)(m0 + r) * 1024 + kt + c);
            As[r][c + 0] = __uint_as_float(f2tf32(v.x));
            As[r][c + 1] = __uint_as_float(f2tf32(v.y));
            As[r][c + 2] = __uint_as_float(f2tf32(v.z));
            As[r][c + 3] = __uint_as_float(f2tf32(v.w));
        }
        // Load B tile 32x128 from W_enc rows (1024+kt .. +31), cols n0..n0+127
#pragma unroll
        for (int i = 0; i < 4; i++) {
            const int q = tid + i * 256;        // 0..1023
            const int r = q >> 5;               // 0..31
            const int c = (q & 31) * 4;         // 0..124
            const float4 v = *(const float4*)(W + (size_t)(1024 + kt + r) * 1024 + n0 + c);
            Bs[r][c + 0] = __uint_as_float(f2tf32(v.x));
            Bs[r][c + 1] = __uint_as_float(f2tf32(v.y));
            Bs[r][c + 2] = __uint_as_float(f2tf32(v.z));
            Bs[r][c + 3] = __uint_as_float(f2tf32(v.w));
        }
        __syncthreads();

#pragma unroll
        for (int ks = 0; ks < 4; ks++) {
            const int kb = ks * 8;
            unsigned a[2][4], bb[8][2];
#pragma unroll
            for (int i = 0; i < 2; i++) {
                const int r  = wm * 32 + i * 16 + (lane >> 2);
                const int cc = kb + (lane & 3);
                a[i][0] = __float_as_uint(As[r][cc]);
                a[i][1] = __float_as_uint(As[r + 8][cc]);
                a[i][2] = __float_as_uint(As[r][cc + 4]);
                a[i][3] = __float_as_uint(As[r + 8][cc + 4]);
            }
#pragma unroll
            for (int j = 0; j < 8; j++) {
                const int cn = wn * 64 + j * 8 + (lane >> 2);
                const int rr = kb + (lane & 3);
                bb[j][0] = __float_as_uint(Bs[rr][cn]);
                bb[j][1] = __float_as_uint(Bs[rr + 4][cn]);
            }
#pragma unroll
            for (int i = 0; i < 2; i++)
#pragma unroll
                for (int j = 0; j < 8; j++) {
                    asm volatile(
                        "mma.sync.aligned.m16n8k8.row.col.f32.tf32.tf32.f32 "
                        "{%0,%1,%2,%3}, {%4,%5,%6,%7}, {%8,%9}, {%0,%1,%2,%3};"
                        : "+f"(acc[i][j][0]), "+f"(acc[i][j][1]),
                          "+f"(acc[i][j][2]), "+f"(acc[i][j][3])
                        : "r"(a[i][0]), "r"(a[i][1]), "r"(a[i][2]), "r"(a[i][3]),
                          "r"(bb[j][0]), "r"(bb[j][1]));
                }
        }
        __syncthreads();
    }

    // Epilogue: energy = tanh(acc + dec_base[b][col]); partial score = sum(energy * v_w)
    const int b = m0 >> 11;                 // m0 / 2048 (128-row tile never crosses batch)
    float eadd[16], vv[16];
#pragma unroll
    for (int j = 0; j < 8; j++)
#pragma unroll
        for (int c = 0; c < 2; c++) {
            const int col = n0 + wn * 64 + j * 8 + (lane & 3) * 2 + c;
            eadd[j * 2 + c] = g_decb[b * DECD + col];
            vv[j * 2 + c]   = vw[col];
        }

#pragma unroll
    for (int i = 0; i < 2; i++)
#pragma unroll
        for (int h = 0; h < 2; h++) {
            float p = 0.f;
#pragma unroll
            for (int j = 0; j < 8; j++)
#pragma unroll
                for (int c = 0; c < 2; c++) {
                    const float v = acc[i][j][h * 2 + c];
                    p += fast_tanh(v + eadd[j * 2 + c]) * vv[j * 2 + c];
                }
            p += __shfl_xor_sync(0xffffffffu, p, 1);
            p += __shfl_xor_sync(0xffffffffu, p, 2);
            if ((lane & 3) == 0) {
                const int row = m0 + wm * 32 + i * 16 + h * 8 + (lane >> 2);
                atomicAdd(&g_scores[row], p);
            }
        }
}

// ---------------------------------------------------------------------------
// Kernel 3: masked softmax over S per batch row -> attn weights in d_out
// ---------------------------------------------------------------------------
__global__ void softmax_kernel(const int* __restrict__ mask,
                               float* __restrict__ out_w) {
    const int b = blockIdx.x;
    const int tid = threadIdx.x;
    __shared__ float red[256];

    float ls[8];
#pragma unroll
    for (int i = 0; i < 8; i++) {
        const int s = tid + i * 256;
        const float sc = g_scores[b * SS + s];
        ls[i] = (mask[b * SS + s] == 0) ? -1e9f : sc;
    }
    float mx = ls[0];
#pragma unroll
    for (int i = 1; i < 8; i++) mx = fmaxf(mx, ls[i]);
    red[tid] = mx;
    __syncthreads();
    for (int off = 128; off > 0; off >>= 1) {
        if (tid < off) red[tid] = fmaxf(red[tid], red[tid + off]);
        __syncthreads();
    }
    mx = red[0];
    __syncthreads();

    float ex[8];
    float sum = 0.f;
#pragma unroll
    for (int i = 0; i < 8; i++) {
        ex[i] = __expf(ls[i] - mx);
        sum += ex[i];
    }
    red[tid] = sum;
    __syncthreads();
    for (int off = 128; off > 0; off >>= 1) {
        if (tid < off) red[tid] += red[tid + off];
        __syncthreads();
    }
    const float inv = 1.f / red[0];
#pragma unroll
    for (int i = 0; i < 8; i++)
        out_w[b * SS + tid + i * 256] = ex[i] * inv;
}

// ---------------------------------------------------------------------------
// Kernel 4: context[b][e] = sum_s w[b][s] * enc[b][s][e]
//   grid (16 s-chunks, 32 b), 256 threads, float4 over e, atomicAdd combine.
// ---------------------------------------------------------------------------
__global__ void context_kernel(const float* __restrict__ enc,
                               const float* __restrict__ w,
                               float* __restrict__ ctx) {
    const int b = blockIdx.y;
    const int ch = blockIdx.x;
    const int tid = threadIdx.x;
    __shared__ float ws[128];
    const int s0 = ch * 128;
    if (tid < 128) ws[tid] = w[b * SS + s0 + tid];
    __syncthreads();

    float ax = 0.f, ay = 0.f, az = 0.f, aw = 0.f;
    const float* base = enc + ((size_t)b * SS + s0) * 1024 + tid * 4;
#pragma unroll 4
    for (int s = 0; s < 128; s++) {
        const float4 v = *(const float4*)(base + (size_t)s * 1024);
        const float wv = ws[s];
        ax += wv * v.x;
        ay += wv * v.y;
        az += wv * v.z;
        aw += wv * v.w;
    }
    float* o = ctx + b * ENCD + tid * 4;
    atomicAdd(o + 0, ax);
    atomicAdd(o + 1, ay);
    atomicAdd(o + 2, az);
    atomicAdd(o + 3, aw);
}

// ---------------------------------------------------------------------------
extern "C" void kernel_launch(void* const* d_in, const int* in_sizes, int n_in,
                              void* d_out, int out_size) {
    const float* dh   = (const float*)d_in[0];   // (32, 1024)
    const float* enc  = (const float*)d_in[1];   // (32, 2048, 1024)
    const int*   mask = (const int*)d_in[2];     // (32, 2048)
    const float* W    = (const float*)d_in[3];   // (2048, 1024)
    const float* ba   = (const float*)d_in[4];   // (1024,)
    const float* vw   = (const float*)d_in[5];   // (1024,)

    float* out  = (float*)d_out;
    float* ctx  = out;                 // (32, 1024)
    float* attw = out + BB * ENCD;     // (32, 2048)

    prep_kernel<<<32, 256>>>(dh, W, ba, ctx);
    score_gemm_kernel<<<dim3(8, 512), 256>>>(enc, W, vw);
    softmax_kernel<<<32, 256>>>(mask, attw);
    context_kernel<<<dim3(16, 32), 256>>>(enc, attw, ctx);
}

// round 3
// speedup vs baseline: 1.3360x; 1.3360x over previous
#include <cuda_runtime.h>
#include <cstdint>

#define BB   32
#define SS   2048
#define ND   1024

// Scratch (allocation-free rule: __device__ globals)
__device__ float g_scores[BB * SS];
__device__ float g_decb[BB * ND];
__device__ float g_Bt[ND * ND];          // W_enc^T, tf32-rounded: Bt[n][k] = rna(W[1024+k][n])

// ---------------------------------------------------------------- helpers
__device__ __forceinline__ float fast_tanh(float x) {
    float y;
    asm("tanh.approx.f32 %0, %1;" : "=f"(y) : "f"(x));
    return y;
}
__device__ __forceinline__ unsigned f2tf32(float x) {
    unsigned o;
    asm("cvt.rna.tf32.f32 %0, %1;" : "=r"(o) : "f"(x));
    return o;
}
__device__ __forceinline__ uint32_t smem_u32(const void* p) {
    uint32_t a;
    asm("{ .reg .u64 t; cvta.to.shared.u64 t, %1; cvt.u32.u64 %0, t; }" : "=r"(a) : "l"(p));
    return a;
}

// ---------------------------------------------------------------------------
// Kernel 0: transpose W_enc -> g_Bt with RNA tf32 rounding
// ---------------------------------------------------------------------------
__global__ void transpose_kernel(const float* __restrict__ W) {
    __shared__ float t[32][33];
    const int kb = blockIdx.x * 32, nb = blockIdx.y * 32;
    const int tx = threadIdx.x, ty = threadIdx.y;
#pragma unroll
    for (int i = 0; i < 32; i += 8) {
        const float v = W[(size_t)(1024 + kb + ty + i) * 1024 + nb + tx];
        t[ty + i][tx] = __uint_as_float(f2tf32(v));
    }
    __syncthreads();
#pragma unroll
    for (int i = 0; i < 32; i += 8)
        g_Bt[(size_t)(nb + ty + i) * 1024 + kb + tx] = t[tx][ty + i];
}

// ---------------------------------------------------------------------------
// Kernel 1: dec_base = dh @ W_dec + b_attn; zero score scratch + ctx output
// ---------------------------------------------------------------------------
__global__ void prep_kernel(const float* __restrict__ dh,
                            const float* __restrict__ W,
                            const float* __restrict__ b_attn,
                            float* __restrict__ out_ctx) {
    const int b = blockIdx.x;
    const int tid = threadIdx.x;

    for (int i = b * 256 + tid; i < BB * SS; i += 32 * 256) g_scores[i] = 0.f;
    for (int i = b * 256 + tid; i < BB * ND; i += 32 * 256) out_ctx[i] = 0.f;

    __shared__ float sh[ND];
    for (int i = tid; i < ND; i += 256) sh[i] = dh[b * ND + i];
    __syncthreads();

    const int d0 = tid;
    float a0 = b_attn[d0];
    float a1 = b_attn[d0 + 256];
    float a2 = b_attn[d0 + 512];
    float a3 = b_attn[d0 + 768];
#pragma unroll 4
    for (int e = 0; e < ND; e++) {
        const float sv = sh[e];
        const float* w = W + (size_t)e * ND + d0;
        a0 += sv * w[0];
        a1 += sv * w[256];
        a2 += sv * w[512];
        a3 += sv * w[768];
    }
    g_decb[b * ND + d0]       = a0;
    g_decb[b * ND + d0 + 256] = a1;
    g_decb[b * ND + d0 + 512] = a2;
    g_decb[b * ND + d0 + 768] = a3;
}

// ---------------------------------------------------------------------------
// Kernel 2: enc_proj GEMM (mma.sync tf32, 128x128 tile, BK=32, double-buffered
//           cp.async) fused with tanh + v-dot -> score partials.
//   K-permutation: logical k of MMA step maps to global k
//       g = (lane&3)*8 + ks*2 + h        (identical for A and B -> exact)
//   so each thread's operands for a whole kt are contiguous 8 floats => LDS.128.
//   smem rows padded to 36 floats: phase-conflict-free for 128-bit loads.
// ---------------------------------------------------------------------------
#define PAD       36
#define ASTAGE    (128 * PAD)                  // floats per A stage
#define GEMM_SMEM (4 * ASTAGE * 4)             // bytes: A0,A1,B0,B1

__global__ __launch_bounds__(256, 2) void score_gemm(const float* __restrict__ enc,
                                                     const float* __restrict__ vw) {
    extern __shared__ float sm[];
    const uint32_t sb = smem_u32(sm);
    const int tid  = threadIdx.x;
    const int lane = tid & 31;
    const int warp = tid >> 5;
    const int wm   = warp >> 1;              // 0..3
    const int wn   = warp & 1;               // 0..1
    const int n0   = blockIdx.x * 128;
    const int m0   = blockIdx.y * 128;

    // stage loader: A 128x32 + B 128x32 (natural k order, 16B cp.async)
    const float* Abase = enc  + (size_t)m0 * 1024;
    const float* Bbase = g_Bt + (size_t)n0 * 1024;
    auto load_stage = [&](int kt, int st) {
        const uint32_t abase = sb + (uint32_t)(st * ASTAGE) * 4;
        const uint32_t bbase = sb + (uint32_t)((2 + st) * ASTAGE) * 4;
        const float* Ag = Abase + kt * 32;
        const float* Bg = Bbase + kt * 32;
#pragma unroll
        for (int i = 0; i < 4; i++) {
            const int q = tid + i * 256;     // 0..1023
            const int r = q >> 3, c = q & 7;
            const uint32_t off = (uint32_t)(r * PAD + c * 4) * 4;
            asm volatile("cp.async.cg.shared.global [%0], [%1], 16;"
                         :: "r"(abase + off), "l"(Ag + (size_t)r * 1024 + c * 4));
            asm volatile("cp.async.cg.shared.global [%0], [%1], 16;"
                         :: "r"(bbase + off), "l"(Bg + (size_t)r * 1024 + c * 4));
        }
        asm volatile("cp.async.commit_group;" ::: "memory");
    };

    float acc[2][8][4];
#pragma unroll
    for (int i = 0; i < 2; i++)
#pragma unroll
        for (int j = 0; j < 8; j++)
#pragma unroll
            for (int c = 0; c < 4; c++) acc[i][j][c] = 0.f;

    load_stage(0, 0);
    load_stage(1, 1);

    const int q8   = (lane & 3) * 8;         // this thread's contiguous k window
    const int ra   = wm * 32 + (lane >> 2);  // A base row for i=0
    const int nb   = wn * 64 + (lane >> 2);  // B base col for j=0

    for (int kt = 0; kt < 32; kt++) {
        const int st = kt & 1;
        if (kt < 30)
            asm volatile("cp.async.wait_group 1;" ::: "memory");
        else
            asm volatile("cp.async.wait_group 0;" ::: "memory");
        __syncthreads();

        const float* As = sm + st * ASTAGE;
        const float* Bs = sm + (2 + st) * ASTAGE;

#pragma unroll
        for (int kh = 0; kh < 2; kh++) {
            const int ko = q8 + kh * 4;
            float av[4][4];                                      // rows ra, ra+8, ra+16, ra+24
            *(float4*)av[0] = *(const float4*)(As + (ra)      * PAD + ko);
            *(float4*)av[1] = *(const float4*)(As + (ra + 8)  * PAD + ko);
            *(float4*)av[2] = *(const float4*)(As + (ra + 16) * PAD + ko);
            *(float4*)av[3] = *(const float4*)(As + (ra + 24) * PAD + ko);

#pragma unroll
            for (int jh = 0; jh < 2; jh++) {
                float bv[4][4];
                *(float4*)bv[0] = *(const float4*)(Bs + (nb + jh * 32)      * PAD + ko);
                *(float4*)bv[1] = *(const float4*)(Bs + (nb + jh * 32 + 8)  * PAD + ko);
                *(float4*)bv[2] = *(const float4*)(Bs + (nb + jh * 32 + 16) * PAD + ko);
                *(float4*)bv[3] = *(const float4*)(Bs + (nb + jh * 32 + 24) * PAD + ko);

#pragma unroll
                for (int i = 0; i < 2; i++)
#pragma unroll
                    for (int j = 0; j < 4; j++)
#pragma unroll
                        for (int ks = 0; ks < 2; ks++) {
                            const int jj = jh * 4 + j;
                            asm volatile(
                                "mma.sync.aligned.m16n8k8.row.col.f32.tf32.tf32.f32 "
                                "{%0,%1,%2,%3}, {%4,%5,%6,%7}, {%8,%9}, {%0,%1,%2,%3};"
                                : "+f"(acc[i][jj][0]), "+f"(acc[i][jj][1]),
                                  "+f"(acc[i][jj][2]), "+f"(acc[i][jj][3])
                                : "r"(__float_as_uint(av[2 * i][2 * ks])),
                                  "r"(__float_as_uint(av[2 * i + 1][2 * ks])),
                                  "r"(__float_as_uint(av[2 * i][2 * ks + 1])),
                                  "r"(__float_as_uint(av[2 * i + 1][2 * ks + 1])),
                                  "r"(__float_as_uint(bv[j][2 * ks])),
                                  "r"(__float_as_uint(bv[j][2 * ks + 1])));
                        }
            }
        }
        __syncthreads();
        if (kt + 2 < 32) load_stage(kt + 2, st);
    }

    // Epilogue: energy = tanh(acc + dec_base[b][col]); score partial = energy . v_w
    const int b = m0 >> 11;
    float eadd[16], vv[16];
#pragma unroll
    for (int j = 0; j < 8; j++)
#pragma unroll
        for (int c = 0; c < 2; c++) {
            const int col = n0 + wn * 64 + j * 8 + (lane & 3) * 2 + c;
            eadd[j * 2 + c] = g_decb[b * ND + col];
            vv[j * 2 + c]   = vw[col];
        }

#pragma unroll
    for (int i = 0; i < 2; i++)
#pragma unroll
        for (int h = 0; h < 2; h++) {
            float p = 0.f;
#pragma unroll
            for (int j = 0; j < 8; j++)
#pragma unroll
                for (int c = 0; c < 2; c++)
                    p += fast_tanh(acc[i][j][h * 2 + c] + eadd[j * 2 + c]) * vv[j * 2 + c];
            p += __shfl_xor_sync(0xffffffffu, p, 1);
            p += __shfl_xor_sync(0xffffffffu, p, 2);
            if ((lane & 3) == 0) {
                const int row = m0 + wm * 32 + i * 16 + h * 8 + (lane >> 2);
                atomicAdd(&g_scores[row], p);
            }
        }
}

// ---------------------------------------------------------------------------
// Kernel 3: masked softmax over S per batch
// ---------------------------------------------------------------------------
__global__ void softmax_kernel(const int* __restrict__ mask,
                               float* __restrict__ out_w) {
    const int b = blockIdx.x;
    const int tid = threadIdx.x;
    __shared__ float red[256];

    float ls[8];
#pragma unroll
    for (int i = 0; i < 8; i++) {
        const int s = tid + i * 256;
        const float sc = g_scores[b * SS + s];
        ls[i] = (mask[b * SS + s] == 0) ? -1e9f : sc;
    }
    float mx = ls[0];
#pragma unroll
    for (int i = 1; i < 8; i++) mx = fmaxf(mx, ls[i]);
    red[tid] = mx;
    __syncthreads();
    for (int off = 128; off > 0; off >>= 1) {
        if (tid < off) red[tid] = fmaxf(red[tid], red[tid + off]);
        __syncthreads();
    }
    mx = red[0];
    __syncthreads();

    float ex[8];
    float sum = 0.f;
#pragma unroll
    for (int i = 0; i < 8; i++) {
        ex[i] = __expf(ls[i] - mx);
        sum += ex[i];
    }
    red[tid] = sum;
    __syncthreads();
    for (int off = 128; off > 0; off >>= 1) {
        if (tid < off) red[tid] += red[tid + off];
        __syncthreads();
    }
    const float inv = 1.f / red[0];
#pragma unroll
    for (int i = 0; i < 8; i++)
        out_w[b * SS + tid + i * 256] = ex[i] * inv;
}

// ---------------------------------------------------------------------------
// Kernel 4: context = attn_weights @ encoder_outputs
// ---------------------------------------------------------------------------
__global__ void context_kernel(const float* __restrict__ enc,
                               const float* __restrict__ w,
                               float* __restrict__ ctx) {
    const int b = blockIdx.y;
    const int ch = blockIdx.x;
    const int tid = threadIdx.x;
    __shared__ float ws[128];
    const int s0 = ch * 128;
    if (tid < 128) ws[tid] = w[b * SS + s0 + tid];
    __syncthreads();

    float ax = 0.f, ay = 0.f, az = 0.f, aw = 0.f;
    const float* base = enc + ((size_t)b * SS + s0) * 1024 + tid * 4;
#pragma unroll 4
    for (int s = 0; s < 128; s++) {
        const float4 v = *(const float4*)(base + (size_t)s * 1024);
        const float wv = ws[s];
        ax += wv * v.x;
        ay += wv * v.y;
        az += wv * v.z;
        aw += wv * v.w;
    }
    float* o = ctx + b * ND + tid * 4;
    atomicAdd(o + 0, ax);
    atomicAdd(o + 1, ay);
    atomicAdd(o + 2, az);
    atomicAdd(o + 3, aw);
}

// ---------------------------------------------------------------------------
extern "C" void kernel_launch(void* const* d_in, const int* in_sizes, int n_in,
                              void* d_out, int out_size) {
    const float* dh   = (const float*)d_in[0];   // (32, 1024)
    const float* enc  = (const float*)d_in[1];   // (32, 2048, 1024)
    const int*   mask = (const int*)d_in[2];     // (32, 2048)
    const float* W    = (const float*)d_in[3];   // (2048, 1024)
    const float* ba   = (const float*)d_in[4];   // (1024,)
    const float* vw   = (const float*)d_in[5];   // (1024,)

    float* out  = (float*)d_out;
    float* ctx  = out;                 // (32, 1024)
    float* attw = out + BB * ND;       // (32, 2048)

    cudaFuncSetAttribute(score_gemm, cudaFuncAttributeMaxDynamicSharedMemorySize, GEMM_SMEM);

    prep_kernel<<<32, 256>>>(dh, W, ba, ctx);
    transpose_kernel<<<dim3(32, 32), dim3(32, 8)>>>(W);
    score_gemm<<<dim3(8, 512), 256, GEMM_SMEM>>>(enc, vw);
    softmax_kernel<<<32, 256>>>(mask, attw);
    context_kernel<<<dim3(16, 32), 256>>>(enc, attw, ctx);
}

// round 4
// speedup vs baseline: 1.7904x; 1.3401x over previous
#include <cuda_runtime.h>
#include <cuda_fp16.h>
#include <cstdint>

#define BB   32
#define SS   2048
#define ND   1024

// Scratch (allocation-free rule: __device__ globals)
__device__ float g_scores[BB * SS];
__device__ float g_decb[BB * ND];
__device__ float g_Bt[ND * ND];          // W_enc^T: Bt[n][k] = W[1024+k][n]

// ---------------------------------------------------------------- helpers
__device__ __forceinline__ float fast_tanh(float x) {
    float y;
    asm("tanh.approx.f32 %0, %1;" : "=f"(y) : "f"(x));
    return y;
}
__device__ __forceinline__ uint32_t smem_u32(const void* p) {
    uint32_t a;
    asm("{ .reg .u64 t; cvta.to.shared.u64 t, %1; cvt.u32.u64 %0, t; }" : "=r"(a) : "l"(p));
    return a;
}
__device__ __forceinline__ uint32_t pack_h2(float a, float b) {
    __half2 h = __floats2half2_rn(a, b);
    return *(uint32_t*)&h;
}

// ---------------------------------------------------------------------------
// Kernel 0: transpose W_enc -> g_Bt
// ---------------------------------------------------------------------------
__global__ void transpose_kernel(const float* __restrict__ W) {
    __shared__ float t[32][33];
    const int kb = blockIdx.x * 32, nb = blockIdx.y * 32;
    const int tx = threadIdx.x, ty = threadIdx.y;
#pragma unroll
    for (int i = 0; i < 32; i += 8)
        t[ty + i][tx] = W[(size_t)(1024 + kb + ty + i) * 1024 + nb + tx];
    __syncthreads();
#pragma unroll
    for (int i = 0; i < 32; i += 8)
        g_Bt[(size_t)(nb + ty + i) * 1024 + kb + tx] = t[tx][ty + i];
}

// ---------------------------------------------------------------------------
// Kernel 1: dec_base = dh @ W_dec + b_attn; zero score scratch + ctx output
// ---------------------------------------------------------------------------
__global__ void prep_kernel(const float* __restrict__ dh,
                            const float* __restrict__ W,
                            const float* __restrict__ b_attn,
                            float* __restrict__ out_ctx) {
    const int b = blockIdx.x;
    const int tid = threadIdx.x;

    for (int i = b * 256 + tid; i < BB * SS; i += 32 * 256) g_scores[i] = 0.f;
    for (int i = b * 256 + tid; i < BB * ND; i += 32 * 256) out_ctx[i] = 0.f;

    __shared__ float sh[ND];
    for (int i = tid; i < ND; i += 256) sh[i] = dh[b * ND + i];
    __syncthreads();

    const int d0 = tid;
    float a0 = b_attn[d0];
    float a1 = b_attn[d0 + 256];
    float a2 = b_attn[d0 + 512];
    float a3 = b_attn[d0 + 768];
#pragma unroll 4
    for (int e = 0; e < ND; e++) {
        const float sv = sh[e];
        const float* w = W + (size_t)e * ND + d0;
        a0 += sv * w[0];
        a1 += sv * w[256];
        a2 += sv * w[512];
        a3 += sv * w[768];
    }
    g_decb[b * ND + d0]       = a0;
    g_decb[b * ND + d0 + 256] = a1;
    g_decb[b * ND + d0 + 512] = a2;
    g_decb[b * ND + d0 + 768] = a3;
}

// ---------------------------------------------------------------------------
// Kernel 2: enc_proj GEMM via fp16 mma.sync m16n8k16 (same 10-bit mantissa as
//   tf32, 2x FLOP/instr), 128x128 tile, BK=32, double-buffered cp.async,
//   fused tanh + v-dot.
//   K-permutation (identical for A and B -> exact): logical k kl maps to
//     g(kl) = ((kl%8)>>1)*8 + (kl>>4)*4 + ((kl>>3)&1)*2 + (kl&1)
//   so each thread's 8 operand k's per k16-step-pair are the contiguous
//   window [ (lane&3)*8, +8 ): two float4 LDS per row, packed to half2.
// ---------------------------------------------------------------------------
#define PAD       36
#define ASTAGE    (128 * PAD)                  // floats per A (or B) stage
#define GEMM_SMEM (4 * ASTAGE * 4)             // bytes: A0,A1,B0,B1

__global__ __launch_bounds__(256, 2) void score_gemm(const float* __restrict__ enc,
                                                     const float* __restrict__ vw) {
    extern __shared__ float sm[];
    const uint32_t sb = smem_u32(sm);
    const int tid  = threadIdx.x;
    const int lane = tid & 31;
    const int warp = tid >> 5;
    const int wm   = warp >> 1;              // 0..3
    const int wn   = warp & 1;               // 0..1
    const int n0   = blockIdx.x * 128;
    const int m0   = blockIdx.y * 128;

    const float* Abase = enc  + (size_t)m0 * 1024;
    const float* Bbase = g_Bt + (size_t)n0 * 1024;
    auto load_stage = [&](int kt, int st) {
        const uint32_t abase = sb + (uint32_t)(st * ASTAGE) * 4;
        const uint32_t bbase = sb + (uint32_t)((2 + st) * ASTAGE) * 4;
        const float* Ag = Abase + kt * 32;
        const float* Bg = Bbase + kt * 32;
#pragma unroll
        for (int i = 0; i < 4; i++) {
            const int q = tid + i * 256;     // 0..1023
            const int r = q >> 3, c = q & 7;
            const uint32_t off = (uint32_t)(r * PAD + c * 4) * 4;
            asm volatile("cp.async.cg.shared.global [%0], [%1], 16;"
                         :: "r"(abase + off), "l"(Ag + (size_t)r * 1024 + c * 4));
            asm volatile("cp.async.cg.shared.global [%0], [%1], 16;"
                         :: "r"(bbase + off), "l"(Bg + (size_t)r * 1024 + c * 4));
        }
        asm volatile("cp.async.commit_group;" ::: "memory");
    };

    float acc[2][8][4];
#pragma unroll
    for (int i = 0; i < 2; i++)
#pragma unroll
        for (int j = 0; j < 8; j++)
#pragma unroll
            for (int c = 0; c < 4; c++) acc[i][j][c] = 0.f;

    load_stage(0, 0);
    load_stage(1, 1);

    const int kw = (lane & 3) * 8;           // this thread's contiguous k window
    const int ra = wm * 32 + (lane >> 2);    // A base row
    const int nb = wn * 64 + (lane >> 2);    // B base col

    for (int kt = 0; kt < 32; kt++) {
        const int st = kt & 1;
        if (kt < 30)
            asm volatile("cp.async.wait_group 1;" ::: "memory");
        else
            asm volatile("cp.async.wait_group 0;" ::: "memory");
        __syncthreads();

        const float* As = sm + st * ASTAGE;
        const float* Bs = sm + (2 + st) * ASTAGE;

        // A: rows ra+{0,8,16,24}; 8 contiguous floats each -> 4 half2 regs
        uint32_t ah[4][4];
#pragma unroll
        for (int rdx = 0; rdx < 4; rdx++) {
            const float* p = As + (ra + 8 * rdx) * PAD + kw;
            const float4 lo = *(const float4*)p;
            const float4 hi = *(const float4*)(p + 4);
            ah[rdx][0] = pack_h2(lo.x, lo.y);
            ah[rdx][1] = pack_h2(lo.z, lo.w);
            ah[rdx][2] = pack_h2(hi.x, hi.y);
            ah[rdx][3] = pack_h2(hi.z, hi.w);
        }
        // B: cols nb + j*8, j=0..7
        uint32_t bh[8][4];
#pragma unroll
        for (int j = 0; j < 8; j++) {
            const float* p = Bs + (nb + j * 8) * PAD + kw;
            const float4 lo = *(const float4*)p;
            const float4 hi = *(const float4*)(p + 4);
            bh[j][0] = pack_h2(lo.x, lo.y);
            bh[j][1] = pack_h2(lo.z, lo.w);
            bh[j][2] = pack_h2(hi.x, hi.y);
            bh[j][3] = pack_h2(hi.z, hi.w);
        }

#pragma unroll
        for (int i = 0; i < 2; i++)
#pragma unroll
            for (int j = 0; j < 8; j++)
#pragma unroll
                for (int s = 0; s < 2; s++) {
                    asm volatile(
                        "mma.sync.aligned.m16n8k16.row.col.f32.f16.f16.f32 "
                        "{%0,%1,%2,%3}, {%4,%5,%6,%7}, {%8,%9}, {%0,%1,%2,%3};"
                        : "+f"(acc[i][j][0]), "+f"(acc[i][j][1]),
                          "+f"(acc[i][j][2]), "+f"(acc[i][j][3])
                        : "r"(ah[2 * i][2 * s]), "r"(ah[2 * i + 1][2 * s]),
                          "r"(ah[2 * i][2 * s + 1]), "r"(ah[2 * i + 1][2 * s + 1]),
                          "r"(bh[j][2 * s]), "r"(bh[j][2 * s + 1]));
                }
        __syncthreads();
        if (kt + 2 < 32) load_stage(kt + 2, st);
    }

    // Epilogue: energy = tanh(acc + dec_base[b][col]); score partial = energy . v_w
    const int b = m0 >> 11;
    float eadd[16], vv[16];
#pragma unroll
    for (int j = 0; j < 8; j++)
#pragma unroll
        for (int c = 0; c < 2; c++) {
            const int col = n0 + wn * 64 + j * 8 + (lane & 3) * 2 + c;
            eadd[j * 2 + c] = g_decb[b * ND + col];
            vv[j * 2 + c]   = vw[col];
        }

#pragma unroll
    for (int i = 0; i < 2; i++)
#pragma unroll
        for (int h = 0; h < 2; h++) {
            float p = 0.f;
#pragma unroll
            for (int j = 0; j < 8; j++)
#pragma unroll
                for (int c = 0; c < 2; c++)
                    p += fast_tanh(acc[i][j][h * 2 + c] + eadd[j * 2 + c]) * vv[j * 2 + c];
            p += __shfl_xor_sync(0xffffffffu, p, 1);
            p += __shfl_xor_sync(0xffffffffu, p, 2);
            if ((lane & 3) == 0) {
                const int row = m0 + wm * 32 + i * 16 + h * 8 + (lane >> 2);
                atomicAdd(&g_scores[row], p);
            }
        }
}

// ---------------------------------------------------------------------------
// Kernel 3: masked softmax over S per batch
// ---------------------------------------------------------------------------
__global__ void softmax_kernel(const int* __restrict__ mask,
                               float* __restrict__ out_w) {
    const int b = blockIdx.x;
    const int tid = threadIdx.x;
    __shared__ float red[256];

    float ls[8];
#pragma unroll
    for (int i = 0; i < 8; i++) {
        const int s = tid + i * 256;
        const float sc = g_scores[b * SS + s];
        ls[i] = (mask[b * SS + s] == 0) ? -1e9f : sc;
    }
    float mx = ls[0];
#pragma unroll
    for (int i = 1; i < 8; i++) mx = fmaxf(mx, ls[i]);
    red[tid] = mx;
    __syncthreads();
    for (int off = 128; off > 0; off >>= 1) {
        if (tid < off) red[tid] = fmaxf(red[tid], red[tid + off]);
        __syncthreads();
    }
    mx = red[0];
    __syncthreads();

    float ex[8];
    float sum = 0.f;
#pragma unroll
    for (int i = 0; i < 8; i++) {
        ex[i] = __expf(ls[i] - mx);
        sum += ex[i];
    }
    red[tid] = sum;
    __syncthreads();
    for (int off = 128; off > 0; off >>= 1) {
        if (tid < off) red[tid] += red[tid + off];
        __syncthreads();
    }
    const float inv = 1.f / red[0];
#pragma unroll
    for (int i = 0; i < 8; i++)
        out_w[b * SS + tid + i * 256] = ex[i] * inv;
}

// ---------------------------------------------------------------------------
// Kernel 4: context = attn_weights @ encoder_outputs
// ---------------------------------------------------------------------------
__global__ void context_kernel(const float* __restrict__ enc,
                               const float* __restrict__ w,
                               float* __restrict__ ctx) {
    const int b = blockIdx.y;
    const int ch = blockIdx.x;
    const int tid = threadIdx.x;
    __shared__ float ws[128];
    const int s0 = ch * 128;
    if (tid < 128) ws[tid] = w[b * SS + s0 + tid];
    __syncthreads();

    float ax = 0.f, ay = 0.f, az = 0.f, aw = 0.f;
    const float* base = enc + ((size_t)b * SS + s0) * 1024 + tid * 4;
#pragma unroll 4
    for (int s = 0; s < 128; s++) {
        const float4 v = *(const float4*)(base + (size_t)s * 1024);
        const float wv = ws[s];
        ax += wv * v.x;
        ay += wv * v.y;
        az += wv * v.z;
        aw += wv * v.w;
    }
    float* o = ctx + b * ND + tid * 4;
    atomicAdd(o + 0, ax);
    atomicAdd(o + 1, ay);
    atomicAdd(o + 2, az);
    atomicAdd(o + 3, aw);
}

// ---------------------------------------------------------------------------
extern "C" void kernel_launch(void* const* d_in, const int* in_sizes, int n_in,
                              void* d_out, int out_size) {
    const float* dh   = (const float*)d_in[0];   // (32, 1024)
    const float* enc  = (const float*)d_in[1];   // (32, 2048, 1024)
    const int*   mask = (const int*)d_in[2];     // (32, 2048)
    const float* W    = (const float*)d_in[3];   // (2048, 1024)
    const float* ba   = (const float*)d_in[4];   // (1024,)
    const float* vw   = (const float*)d_in[5];   // (1024,)

    float* out  = (float*)d_out;
    float* ctx  = out;                 // (32, 1024)
    float* attw = out + BB * ND;       // (32, 2048)

    cudaFuncSetAttribute(score_gemm, cudaFuncAttributeMaxDynamicSharedMemorySize, GEMM_SMEM);

    prep_kernel<<<32, 256>>>(dh, W, ba, ctx);
    transpose_kernel<<<dim3(32, 32), dim3(32, 8)>>>(W);
    score_gemm<<<dim3(8, 512), 256, GEMM_SMEM>>>(enc, vw);
    softmax_kernel<<<32, 256>>>(mask, attw);
    context_kernel<<<dim3(16, 32), 256>>>(enc, attw, ctx);
}

// round 5
// speedup vs baseline: 2.3588x; 1.3175x over previous
#include <cuda_runtime.h>
#include <cuda_fp16.h>
#include <cstdint>

#define BB   32
#define SS   2048
#define ND   1024

// Scratch (allocation-free rule: __device__ globals)
__device__ float  g_scores[BB * SS];
__device__ float  g_decb[BB * ND];
__device__ __half g_Bth[ND * ND];        // W_enc^T in fp16: Bth[n][k] = W[1024+k][n]

// ---------------------------------------------------------------- helpers
__device__ __forceinline__ float fast_tanh(float x) {
    float y;
    asm("tanh.approx.f32 %0, %1;" : "=f"(y) : "f"(x));
    return y;
}
__device__ __forceinline__ uint32_t smem_u32(const void* p) {
    uint32_t a;
    asm("{ .reg .u64 t; cvta.to.shared.u64 t, %1; cvt.u32.u64 %0, t; }" : "=r"(a) : "l"(p));
    return a;
}
__device__ __forceinline__ uint32_t pack_h2(float a, float b) {
    __half2 h = __floats2half2_rn(a, b);
    return *(uint32_t*)&h;
}

// ---------------------------------------------------------------------------
// Kernel 0: transpose W_enc -> g_Bth (fp16)
// ---------------------------------------------------------------------------
__global__ void transpose_kernel(const float* __restrict__ W) {
    __shared__ float t[32][33];
    const int kb = blockIdx.x * 32, nb = blockIdx.y * 32;
    const int tx = threadIdx.x, ty = threadIdx.y;
#pragma unroll
    for (int i = 0; i < 32; i += 8)
        t[ty + i][tx] = W[(size_t)(1024 + kb + ty + i) * 1024 + nb + tx];
    __syncthreads();
#pragma unroll
    for (int i = 0; i < 32; i += 8)
        g_Bth[(size_t)(nb + ty + i) * 1024 + kb + tx] = __float2half_rn(t[tx][ty + i]);
}

// ---------------------------------------------------------------------------
// Kernel 1: dec_base = dh @ W_dec + b_attn; zero score scratch + ctx output
// ---------------------------------------------------------------------------
__global__ void prep_kernel(const float* __restrict__ dh,
                            const float* __restrict__ W,
                            const float* __restrict__ b_attn,
                            float* __restrict__ out_ctx) {
    const int b = blockIdx.x;
    const int tid = threadIdx.x;

    for (int i = b * 256 + tid; i < BB * SS; i += 32 * 256) g_scores[i] = 0.f;
    for (int i = b * 256 + tid; i < BB * ND; i += 32 * 256) out_ctx[i] = 0.f;

    __shared__ float sh[ND];
    for (int i = tid; i < ND; i += 256) sh[i] = dh[b * ND + i];
    __syncthreads();

    const int d0 = tid;
    float a0 = b_attn[d0];
    float a1 = b_attn[d0 + 256];
    float a2 = b_attn[d0 + 512];
    float a3 = b_attn[d0 + 768];
#pragma unroll 4
    for (int e = 0; e < ND; e++) {
        const float sv = sh[e];
        const float* w = W + (size_t)e * ND + d0;
        a0 += sv * w[0];
        a1 += sv * w[256];
        a2 += sv * w[512];
        a3 += sv * w[768];
    }
    g_decb[b * ND + d0]       = a0;
    g_decb[b * ND + d0 + 256] = a1;
    g_decb[b * ND + d0 + 512] = a2;
    g_decb[b * ND + d0 + 768] = a3;
}

// ---------------------------------------------------------------------------
// Kernel 2: enc_proj GEMM via fp16 mma.sync m16n8k16, 128x128 tile, BK=32,
//   double-buffered cp.async, fused tanh + v-dot.
//   A in smem as fp32 (pad-36 rows), packed to half2 in regs (16 F2FP/kt).
//   B in smem as fp16, 64B rows, no pad (phase-conflict-free for LDS.128).
//   K-permutation identical on A and B (exact): each thread's k-window is the
//   contiguous 8 k's starting at (lane&3)*8.
// ---------------------------------------------------------------------------
#define PAD       36
#define ASTAGE    (128 * PAD)                         // floats per A stage
#define BSTB      8192                                // bytes per B stage
#define AOFF0     0
#define BOFF0     (2 * ASTAGE * 4)                    // after both A stages
#define GEMM_SMEM (2 * ASTAGE * 4 + 2 * BSTB)

__global__ __launch_bounds__(256, 2) void score_gemm(const float* __restrict__ enc,
                                                     const float* __restrict__ vw) {
    extern __shared__ float sm[];
    const uint32_t sb = smem_u32(sm);
    const int tid  = threadIdx.x;
    const int lane = tid & 31;
    const int warp = tid >> 5;
    const int wm   = warp >> 1;              // 0..3
    const int wn   = warp & 1;               // 0..1
    const int n0   = blockIdx.x * 128;
    const int m0   = blockIdx.y * 128;

    const float*  Abase = enc + (size_t)m0 * 1024;
    const __half* Bbase = g_Bth + (size_t)n0 * 1024;

    auto load_stage = [&](int kt, int st) {
        const uint32_t abase = sb + AOFF0 + (uint32_t)(st * ASTAGE) * 4;
        const uint32_t bbase = sb + BOFF0 + (uint32_t)(st * BSTB);
        const float* Ag = Abase + kt * 32;
#pragma unroll
        for (int i = 0; i < 4; i++) {
            const int q = tid + i * 256;     // 0..1023
            const int r = q >> 3, c = q & 7;
            asm volatile("cp.async.cg.shared.global [%0], [%1], 16;"
                         :: "r"(abase + (uint32_t)(r * PAD + c * 4) * 4),
                            "l"(Ag + (size_t)r * 1024 + c * 4));
        }
        const __half* Bg = Bbase + kt * 32;
#pragma unroll
        for (int i = 0; i < 2; i++) {
            const int q = tid + i * 256;     // 0..511
            const int r = q >> 2, c = q & 3; // row 0..127, 16B chunk 0..3
            asm volatile("cp.async.cg.shared.global [%0], [%1], 16;"
                         :: "r"(bbase + (uint32_t)(r * 64 + c * 16)),
                            "l"(Bg + (size_t)r * 1024 + c * 8));
        }
        asm volatile("cp.async.commit_group;" ::: "memory");
    };

    float acc[2][8][4];
#pragma unroll
    for (int i = 0; i < 2; i++)
#pragma unroll
        for (int j = 0; j < 8; j++)
#pragma unroll
            for (int c = 0; c < 4; c++) acc[i][j][c] = 0.f;

    load_stage(0, 0);
    load_stage(1, 1);

    const int kw = (lane & 3) * 8;           // contiguous k window (8 k's)
    const int ra = wm * 32 + (lane >> 2);    // A base row
    const int nb = wn * 64 + (lane >> 2);    // B base col

    for (int kt = 0; kt < 32; kt++) {
        const int st = kt & 1;
        if (kt < 30)
            asm volatile("cp.async.wait_group 1;" ::: "memory");
        else
            asm volatile("cp.async.wait_group 0;" ::: "memory");
        __syncthreads();

        const float* As = sm + st * ASTAGE;
        const uint32_t Bsb = sb + BOFF0 + (uint32_t)(st * BSTB);

        // A: rows ra+{0,8,16,24}, 8 contiguous fp32 -> pack to 4 half2 regs each
        uint32_t ah[4][4];
#pragma unroll
        for (int rdx = 0; rdx < 4; rdx++) {
            const float* p = As + (ra + 8 * rdx) * PAD + kw;
            const float4 lo = *(const float4*)p;
            const float4 hi = *(const float4*)(p + 4);
            ah[rdx][0] = pack_h2(lo.x, lo.y);
            ah[rdx][1] = pack_h2(lo.z, lo.w);
            ah[rdx][2] = pack_h2(hi.x, hi.y);
            ah[rdx][3] = pack_h2(hi.z, hi.w);
        }
        // B: cols nb + j*8; 8 contiguous halfs = one 16B LDS each
        uint32_t bh[8][4];
#pragma unroll
        for (int j = 0; j < 8; j++) {
            const uint32_t addr = Bsb + (uint32_t)((nb + j * 8) * 64 + (lane & 3) * 16);
            asm volatile("ld.shared.v4.u32 {%0,%1,%2,%3}, [%4];"
                         : "=r"(bh[j][0]), "=r"(bh[j][1]), "=r"(bh[j][2]), "=r"(bh[j][3])
                         : "r"(addr));
        }

#pragma unroll
        for (int i = 0; i < 2; i++)
#pragma unroll
            for (int j = 0; j < 8; j++)
#pragma unroll
                for (int s = 0; s < 2; s++) {
                    asm volatile(
                        "mma.sync.aligned.m16n8k16.row.col.f32.f16.f16.f32 "
                        "{%0,%1,%2,%3}, {%4,%5,%6,%7}, {%8,%9}, {%0,%1,%2,%3};"
                        : "+f"(acc[i][j][0]), "+f"(acc[i][j][1]),
                          "+f"(acc[i][j][2]), "+f"(acc[i][j][3])
                        : "r"(ah[2 * i][2 * s]), "r"(ah[2 * i + 1][2 * s]),
                          "r"(ah[2 * i][2 * s + 1]), "r"(ah[2 * i + 1][2 * s + 1]),
                          "r"(bh[j][2 * s]), "r"(bh[j][2 * s + 1]));
                }
        __syncthreads();
        if (kt + 2 < 32) load_stage(kt + 2, st);
    }

    // Epilogue: energy = tanh(acc + dec_base[b][col]); score partial = energy . v_w
    const int b = m0 >> 11;
    float eadd[16], vv[16];
#pragma unroll
    for (int j = 0; j < 8; j++)
#pragma unroll
        for (int c = 0; c < 2; c++) {
            const int col = n0 + wn * 64 + j * 8 + (lane & 3) * 2 + c;
            eadd[j * 2 + c] = g_decb[b * ND + col];
            vv[j * 2 + c]   = vw[col];
        }

#pragma unroll
    for (int i = 0; i < 2; i++)
#pragma unroll
        for (int h = 0; h < 2; h++) {
            float p = 0.f;
#pragma unroll
            for (int j = 0; j < 8; j++)
#pragma unroll
                for (int c = 0; c < 2; c++)
                    p += fast_tanh(acc[i][j][h * 2 + c] + eadd[j * 2 + c]) * vv[j * 2 + c];
            p += __shfl_xor_sync(0xffffffffu, p, 1);
            p += __shfl_xor_sync(0xffffffffu, p, 2);
            if ((lane & 3) == 0) {
                const int row = m0 + wm * 32 + i * 16 + h * 8 + (lane >> 2);
                atomicAdd(&g_scores[row], p);
            }
        }
}

// ---------------------------------------------------------------------------
// Kernel 3: masked softmax over S per batch
// ---------------------------------------------------------------------------
__global__ void softmax_kernel(const int* __restrict__ mask,
                               float* __restrict__ out_w) {
    const int b = blockIdx.x;
    const int tid = threadIdx.x;
    __shared__ float red[256];

    float ls[8];
#pragma unroll
    for (int i = 0; i < 8; i++) {
        const int s = tid + i * 256;
        const float sc = g_scores[b * SS + s];
        ls[i] = (mask[b * SS + s] == 0) ? -1e9f : sc;
    }
    float mx = ls[0];
#pragma unroll
    for (int i = 1; i < 8; i++) mx = fmaxf(mx, ls[i]);
    red[tid] = mx;
    __syncthreads();
    for (int off = 128; off > 0; off >>= 1) {
        if (tid < off) red[tid] = fmaxf(red[tid], red[tid + off]);
        __syncthreads();
    }
    mx = red[0];
    __syncthreads();

    float ex[8];
    float sum = 0.f;
#pragma unroll
    for (int i = 0; i < 8; i++) {
        ex[i] = __expf(ls[i] - mx);
        sum += ex[i];
    }
    red[tid] = sum;
    __syncthreads();
    for (int off = 128; off > 0; off >>= 1) {
        if (tid < off) red[tid] += red[tid + off];
        __syncthreads();
    }
    const float inv = 1.f / red[0];
#pragma unroll
    for (int i = 0; i < 8; i++)
        out_w[b * SS + tid + i * 256] = ex[i] * inv;
}

// ---------------------------------------------------------------------------
// Kernel 4: context = attn_weights @ encoder_outputs  (fp32 path, exact)
// ---------------------------------------------------------------------------
__global__ void context_kernel(const float* __restrict__ enc,
                               const float* __restrict__ w,
                               float* __restrict__ ctx) {
    const int b = blockIdx.y;
    const int ch = blockIdx.x;
    const int tid = threadIdx.x;
    __shared__ float ws[128];
    const int s0 = ch * 128;
    if (tid < 128) ws[tid] = w[b * SS + s0 + tid];
    __syncthreads();

    float ax = 0.f, ay = 0.f, az = 0.f, aw = 0.f;
    const float* base = enc + ((size_t)b * SS + s0) * 1024 + tid * 4;
#pragma unroll 4
    for (int s = 0; s < 128; s++) {
        const float4 v = *(const float4*)(base + (size_t)s * 1024);
        const float wv = ws[s];
        ax += wv * v.x;
        ay += wv * v.y;
        az += wv * v.z;
        aw += wv * v.w;
    }
    float* o = ctx + b * ND + tid * 4;
    atomicAdd(o + 0, ax);
    atomicAdd(o + 1, ay);
    atomicAdd(o + 2, az);
    atomicAdd(o + 3, aw);
}

// ---------------------------------------------------------------------------
extern "C" void kernel_launch(void* const* d_in, const int* in_sizes, int n_in,
                              void* d_out, int out_size) {
    const float* dh   = (const float*)d_in[0];   // (32, 1024)
    const float* enc  = (const float*)d_in[1];   // (32, 2048, 1024)
    const int*   mask = (const int*)d_in[2];     // (32, 2048)
    const float* W    = (const float*)d_in[3];   // (2048, 1024)
    const float* ba   = (const float*)d_in[4];   // (1024,)
    const float* vw   = (const float*)d_in[5];   // (1024,)

    float* out  = (float*)d_out;
    float* ctx  = out;                 // (32, 1024)
    float* attw = out + BB * ND;       // (32, 2048)

    cudaFuncSetAttribute(score_gemm, cudaFuncAttributeMaxDynamicSharedMemorySize, GEMM_SMEM);

    prep_kernel<<<32, 256>>>(dh, W, ba, ctx);
    transpose_kernel<<<dim3(32, 32), dim3(32, 8)>>>(W);
    score_gemm<<<dim3(8, 512), 256, GEMM_SMEM>>>(enc, vw);
    softmax_kernel<<<32, 256>>>(mask, attw);
    context_kernel<<<dim3(16, 32), 256>>>(enc, attw, ctx);
}